// round 17
// baseline (speedup 1.0000x reference)
#include <cuda_runtime.h>
#include <cuda_fp16.h>
#include <math.h>

#define NN 100000
#define NE 1600000
#define ET 1700000          // NE + NN self loops
#define NB 98               // ceil(NN/1024)

// GEMM tiling
#define BM 128
#define BN 64
#define BK 16

#define GTILES 1564         // 782 x 2 tiles for the 128-col GEMM
#define CONVB 6641          // ceil(ET/256) convert blocks
#define FUSEB (GTILES * 5)  // gemm blocks sit at bx%5==0, bx<FUSEB

// ---------------- static scratch (no allocations allowed) ----------------
__device__ __align__(256) __half g_hlh[NN * 128];   // hl fp16 (edge gather)
__device__ __align__(256) float  g_hr[NN * 128];
__device__ __align__(256) float  g_h [NN * 128];
__device__ __align__(256) __half g_wth[6 * 16384];  // W^T [oc][128], fp16
__device__ int g_deg[NN];
__device__ int g_tmp[NN];
__device__ int g_rowptr[NN + 1];
__device__ int g_fill[NN];
__device__ int g_esrc[ET];
__device__ int g_src[ET];
__device__ int g_dst[ET];
__device__ int g_bsums[128];
__device__ int g_is64;

// ---------------- setup: zero deg, detect dtype (parallel), convert W ----
__global__ void zero_detect_k(const int* __restrict__ ei32,
                              const float* __restrict__ W0l, const float* __restrict__ W0r,
                              const float* __restrict__ W1l, const float* __restrict__ W1r,
                              const float* __restrict__ W2l, const float* __restrict__ W2r) {
    int i = blockIdx.x * blockDim.x + threadIdx.x;
    if (i < NN) g_deg[i] = 0;
    if (blockIdx.x == 0 && threadIdx.x < 32) {
        int acc = 0;
        for (int j = threadIdx.x; j < 1024; j += 32) acc |= ei32[2 * j + 1];
#pragma unroll
        for (int off = 16; off > 0; off >>= 1)
            acc |= __shfl_xor_sync(0xffffffffu, acc, off);
        if (threadIdx.x == 0) g_is64 = (acc == 0) ? 1 : 0;
    }
    // W transpose + fp16 convert: Wt[oc][128] so k runs contiguous
    if (i < 4 * 16384) {
        int mat = i >> 14, idx = i & 16383;
        const float* Ws[4] = {W0l, W0r, W1l, W1r};
        float w = Ws[mat][idx];
        int k = idx >> 7, o = idx & 127;        // src W[k][128]
        g_wth[mat * 16384 + o * 128 + k] = __float2half_rn(w);
    } else if (i < 4 * 16384 + 2 * 8192) {
        int j = i - 65536;
        int mat = 4 + (j >> 13), idx = j & 8191;
        const float* Ws2[2] = {W2l, W2r};
        float w = Ws2[mat - 4][idx];
        int k = idx >> 6, o = idx & 63;         // src W2[k][64]
        g_wth[mat * 16384 + o * 128 + k] = __float2half_rn(w);
    }
}

__global__ void scan1_k() {
    __shared__ int sh[1024];
    int i = blockIdx.x * 1024 + threadIdx.x;
    int v = (i < NN) ? g_deg[i] : 0;
    sh[threadIdx.x] = v;
    __syncthreads();
    for (int off = 1; off < 1024; off <<= 1) {
        int t = (threadIdx.x >= off) ? sh[threadIdx.x - off] : 0;
        __syncthreads();
        sh[threadIdx.x] += t;
        __syncthreads();
    }
    if (i < NN) g_tmp[i] = sh[threadIdx.x];
    if (threadIdx.x == 1023) g_bsums[blockIdx.x] = sh[1023];
}

// fused scan2+scan3
__global__ void scan3_k() {
    __shared__ int pref[NB + 1];
    if (threadIdx.x == 0) {
        int acc = 0;
        for (int b = 0; b < NB; b++) { pref[b] = acc; acc += g_bsums[b]; }
    }
    __syncthreads();
    int i = blockIdx.x * blockDim.x + threadIdx.x;
    if (i < NN) {
        int incl = g_tmp[i] + pref[i >> 10];
        g_rowptr[i + 1] = incl;
        g_fill[i] = incl - g_deg[i];           // exclusive prefix = fill cursor
    }
    if (i == 0) g_rowptr[0] = 0;
}

__global__ void scatter_k() {
    int i = blockIdx.x * blockDim.x + threadIdx.x;
    if (i >= ET) return;
    int pos = atomicAdd(&g_fill[g_dst[i]], 1);
    g_esrc[pos] = g_src[i];
}

// ---------------- plain-fp16 dual tensor-core GEMM body -------------------
__device__ __forceinline__ void mma16(float* c, const unsigned* a,
                                      unsigned b0, unsigned b1) {
    asm volatile(
        "mma.sync.aligned.m16n8k16.row.col.f32.f16.f16.f32 "
        "{%0,%1,%2,%3}, {%4,%5,%6,%7}, {%8,%9}, {%0,%1,%2,%3};"
        : "+f"(c[0]), "+f"(c[1]), "+f"(c[2]), "+f"(c[3])
        : "r"(a[0]), "r"(a[1]), "r"(a[2]), "r"(a[3]), "r"(b0), "r"(b1));
}

__device__ __forceinline__ void cp16(unsigned dst, const void* src, int srcBytes) {
    asm volatile("cp.async.ca.shared.global [%0], [%1], 16, %2;"
                 :: "r"(dst), "l"(src), "r"(srcBytes));
}

__device__ __forceinline__ unsigned pack2(float x, float y) {
    __half2 h = __floats2half2_rn(x, y);
    return *reinterpret_cast<unsigned*>(&h);
}

__device__ __forceinline__ unsigned ldb(const __half* buf, int row, int u) {
    int idx = row * 8 + (u ^ (((row >> 2) & 1) << 2));
    return reinterpret_cast<const unsigned*>(buf)[idx];
}

// 3-stage cp.async pipeline, ONE __syncthreads per k-iteration.
__device__ __forceinline__ void gemm_tile_body(
    const float* __restrict__ A,
    const __half* __restrict__ Blh, const __half* __restrict__ Brh,
    __half* __restrict__ Cl, float* __restrict__ Cr,
    int n, int oc, int row0, int col0)
{
    __shared__ float  As[3][BM * 16];                 // fp32 A, XOR-swizzled
    __shared__ __half Bsh[3][2][BN * 16];             // [stage][side]

    const int tid = threadIdx.x;
    const int lane = tid & 31, wid = tid >> 5;
    const int wm = wid >> 1, wn = wid & 1;       // 4 x 2 warp grid
    const int gid = lane >> 2, tig = lane & 3;

    float acc[2][2][4][4];
#pragma unroll
    for (int sd = 0; sd < 2; sd++)
#pragma unroll
        for (int i = 0; i < 2; i++)
#pragma unroll
            for (int j = 0; j < 4; j++)
#pragma unroll
                for (int r = 0; r < 4; r++) acc[sd][i][j][r] = 0.f;

    const int ar = tid >> 1, kof = (tid & 1) * 8;      // A: 2x16B per thread
    const int aswz = 4 * (ar & 3);
    const int aValid = (row0 + ar < n) ? 16 : 0;
    const int bt = tid & 127, bside = tid >> 7;        // B halves
    const int brr = bt >> 1, bcc = bt & 1;
    const int bOff = brr * 32 + 16 * (bcc ^ ((brr >> 2) & 1));  // bytes

    auto load_stage = [&](int st, int kk) {
        const float* srcA = A + (size_t)(row0 + ar) * 128 + kk + kof;
        cp16((unsigned)__cvta_generic_to_shared(&As[st][ar * 16 + (kof ^ aswz)]),
             srcA, aValid);
        cp16((unsigned)__cvta_generic_to_shared(&As[st][ar * 16 + ((kof + 4) ^ aswz)]),
             srcA + 4, aValid);
        const __half* Bsrc = (bside == 0) ? Blh : Brh;
        const __half* sh = Bsrc + (size_t)(col0 + brr) * 128 + kk + 8 * bcc;
        cp16((unsigned)__cvta_generic_to_shared(
                 reinterpret_cast<char*>(Bsh[st][bside]) + bOff), sh, 16);
    };

    load_stage(0, 0);
    asm volatile("cp.async.commit_group;");
    load_stage(1, BK);
    asm volatile("cp.async.commit_group;");

    const int kp0 = 2 * tig;
#pragma unroll
    for (int it = 0; it < 8; it++) {
        const int buf = it % 3;
        if (it == 7) asm volatile("cp.async.wait_group 0;");
        else         asm volatile("cp.async.wait_group 1;");
        __syncthreads();

        unsigned ah[2][4];
#pragma unroll
        for (int i = 0; i < 2; i++) {
            const int m0 = wm * 32 + i * 16;
            const int r0 = m0 + gid, r1 = r0 + 8;
            const int s0 = 4 * (r0 & 3), s1 = 4 * (r1 & 3);
            float2 f0 = *reinterpret_cast<const float2*>(&As[buf][r0 * 16 + (kp0 ^ s0)]);
            float2 f1 = *reinterpret_cast<const float2*>(&As[buf][r1 * 16 + (kp0 ^ s1)]);
            float2 f2 = *reinterpret_cast<const float2*>(&As[buf][r0 * 16 + ((kp0 + 8) ^ s0)]);
            float2 f3 = *reinterpret_cast<const float2*>(&As[buf][r1 * 16 + ((kp0 + 8) ^ s1)]);
            ah[i][0] = pack2(f0.x, f0.y);
            ah[i][1] = pack2(f1.x, f1.y);
            ah[i][2] = pack2(f2.x, f2.y);
            ah[i][3] = pack2(f3.x, f3.y);
        }

#pragma unroll
        for (int j = 0; j < 4; j++) {
            const int c = wn * 32 + j * 8 + gid;
            unsigned bh0 = ldb(Bsh[buf][0], c, tig);
            unsigned bh1 = ldb(Bsh[buf][0], c, tig + 4);
            unsigned rh0 = ldb(Bsh[buf][1], c, tig);
            unsigned rh1 = ldb(Bsh[buf][1], c, tig + 4);
#pragma unroll
            for (int i = 0; i < 2; i++) {
                mma16(acc[0][i][j], ah[i], bh0, bh1);   // L
                mma16(acc[1][i][j], ah[i], rh0, rh1);   // R
            }
        }

        if (it + 2 < 8) {
            load_stage((it + 2) % 3, (it + 2) * BK);
            asm volatile("cp.async.commit_group;");
        }
    }

#pragma unroll
    for (int i = 0; i < 2; i++) {
        int rbase = row0 + wm * 32 + i * 16 + gid;
#pragma unroll
        for (int j = 0; j < 4; j++) {
            int c = col0 + wn * 32 + j * 8 + 2 * tig;
            if (rbase < n) {
                *reinterpret_cast<__half2*>(Cl + (size_t)rbase * oc + c) =
                    __floats2half2_rn(acc[0][i][j][0], acc[0][i][j][1]);
                *reinterpret_cast<float2*>(Cr + (size_t)rbase * oc + c) =
                    make_float2(acc[1][i][j][0], acc[1][i][j][1]);
            }
            if (rbase + 8 < n) {
                *reinterpret_cast<__half2*>(Cl + (size_t)(rbase + 8) * oc + c) =
                    __floats2half2_rn(acc[0][i][j][2], acc[0][i][j][3]);
                *reinterpret_cast<float2*>(Cr + (size_t)(rbase + 8) * oc + c) =
                    make_float2(acc[1][i][j][2], acc[1][i][j][3]);
            }
        }
    }
}

__global__ __launch_bounds__(256, 2) void gemm_dual_k(
    const float* __restrict__ A,
    const __half* __restrict__ Blh, const __half* __restrict__ Brh,
    __half* __restrict__ Cl, float* __restrict__ Cr, int n, int oc)
{
    gemm_tile_body(A, Blh, Brh, Cl, Cr, n, oc,
                   blockIdx.x * BM, blockIdx.y * BN);
}

// fused: layer-0 GEMM tiles interleaved with edge-index conversion + counting.
__global__ __launch_bounds__(256, 2) void gemm0_conv_k(
    const float* __restrict__ A,
    const __half* __restrict__ Blh, const __half* __restrict__ Brh,
    __half* __restrict__ Cl, float* __restrict__ Cr,
    const void* __restrict__ ei)
{
    const int bx = blockIdx.x;
    const bool isGemm = (bx < FUSEB) && (bx % 5 == 0);
    if (!isGemm) {
        int c = (bx < FUSEB) ? bx - (bx + 4) / 5 : bx - GTILES;
        int i = c * 256 + threadIdx.x;
        if (i < ET) {
            int s, d;
            if (i < NE) {
                if (g_is64) {
                    s = (int)((const long long*)ei)[i];
                    d = (int)((const long long*)ei)[NE + i];
                } else {
                    s = ((const int*)ei)[i];
                    d = ((const int*)ei)[NE + i];
                }
            } else {
                s = d = i - NE;
            }
            s = min(max(s, 0), NN - 1);
            d = min(max(d, 0), NN - 1);
            g_src[i] = s;
            g_dst[i] = d;
            atomicAdd(&g_deg[d], 1);
        }
        return;
    }
    const int t = bx / 5;
    gemm_tile_body(A, Blh, Brh, Cl, Cr, NN, 128,
                   (t % 782) * BM, (t / 782) * BN);
}

// ---------------- edge kernel: TWO edges per warp (16 lanes each) ---------
// Each half-warp owns a contiguous half of the node's edge list. All shuffles
// inside the (divergent) loop use the HALF-ONLY mask; the cross-half merge
// happens after both loops reconverge.
template <int H, int CH>
__global__ __launch_bounds__(256) void gat_edge(
    const __half* __restrict__ hl, const float* __restrict__ hr,
    const float* __restrict__ att, const float* __restrict__ bias,
    float* __restrict__ out)
{
    constexpr int V = CH / 16;                  // 8 for CH=128, 4 for CH=64
    const int w = (blockIdx.x * blockDim.x + threadIdx.x) >> 5;
    const int lane = threadIdx.x & 31;
    const int l16 = lane & 15;
    const int half = lane >> 4;
    if (w >= NN) return;

    const unsigned hmask = 0xffffu << (half << 4);   // this half's lanes only

    float attv[V], hrv[V], acc[V];
#pragma unroll
    for (int v = 0; v < V; v++)
        attv[v] = att[l16 * V + v] * 1.4426950408889634f;   // fold log2(e)

    if (V == 8) {
        float4 a = __ldg(reinterpret_cast<const float4*>(hr) + w * 32 + l16 * 2);
        float4 b = __ldg(reinterpret_cast<const float4*>(hr) + w * 32 + l16 * 2 + 1);
        hrv[0] = a.x; hrv[1] = a.y; hrv[2] = a.z; hrv[3] = a.w;
        hrv[4] = b.x; hrv[5] = b.y; hrv[6] = b.z; hrv[7] = b.w;
    } else {
        float4 a = __ldg(reinterpret_cast<const float4*>(hr) + w * 16 + l16);
        hrv[0] = a.x; hrv[1] = a.y; hrv[2] = a.z; hrv[3] = a.w;
    }
#pragma unroll
    for (int v = 0; v < V; v++) acc[v] = 0.f;

    auto graw = [&](int s) -> uint4 {
        uint4 r;
        if (V == 8) {
            r = __ldg(reinterpret_cast<const uint4*>(hl) + s * 16 + l16);
        } else {
            uint2 q = __ldg(reinterpret_cast<const uint2*>(hl) + s * 16 + l16);
            r.x = q.x; r.y = q.y; r.z = 0; r.w = 0;
        }
        return r;
    };
    auto tof = [&](uint4 t, float* hv) {
        float2 f;
        f = __half22float2(*reinterpret_cast<__half2*>(&t.x)); hv[0] = f.x; hv[1] = f.y;
        f = __half22float2(*reinterpret_cast<__half2*>(&t.y)); hv[2] = f.x; hv[3] = f.y;
        if (V == 8) {
            f = __half22float2(*reinterpret_cast<__half2*>(&t.z)); hv[4] = f.x; hv[5] = f.y;
            f = __half22float2(*reinterpret_cast<__half2*>(&t.w)); hv[6] = f.x; hv[7] = f.y;
        }
    };
    auto score = [&](const float* hv) {       // log2(e) * raw score, per head
        float p = 0.f;
#pragma unroll
        for (int v = 0; v < V; v++) {
            float t = hv[v] + hrv[v];
            t = fmaxf(t, 0.2f * t);                 // LeakyReLU(0.2)
            p = fmaf(t, attv[v], p);
        }
#pragma unroll
        for (int off = (16 / H) >> 1; off > 0; off >>= 1)
            p += __shfl_xor_sync(hmask, p, off);    // half-local reduction
        return p;
    };

    float p_self;
    {
        float hs[V];
        tof(graw(w), hs);
        p_self = score(hs);
    }

    float lsum = 0.f;
    auto update = [&](uint4 raw) {
        float hv[V];
        tof(raw, hv);
        float p = score(hv);
        float ww = exp2f(p - p_self);
        lsum += ww;
#pragma unroll
        for (int v = 0; v < V; v++) acc[v] = fmaf(ww, hv[v], acc[v]);
    };

    // contiguous split: half 0 gets ceil(deg/2), half 1 the rest
    const int e0 = g_rowptr[w], e1 = g_rowptr[w + 1];
    const int cnt0 = (e1 - e0 + 1) >> 1;
    int eb = half ? (e0 + cnt0) : e0;
    int ee = half ? e1 : (e0 + cnt0);

    int e = eb;
    for (; e + 4 <= ee; e += 4) {
        int s0 = __ldg(&g_esrc[e]);
        int s1 = __ldg(&g_esrc[e + 1]);
        int s2 = __ldg(&g_esrc[e + 2]);
        int s3 = __ldg(&g_esrc[e + 3]);
        uint4 r0 = graw(s0), r1 = graw(s1), r2 = graw(s2), r3 = graw(s3);
        update(r0); update(r1); update(r2); update(r3);
    }
    for (; e < ee; e++) {
        update(graw(__ldg(&g_esrc[e])));
    }

    // merge the two halves (both loops complete -> warp reconverged)
    lsum += __shfl_xor_sync(0xffffffffu, lsum, 16);
#pragma unroll
    for (int v = 0; v < V; v++)
        acc[v] += __shfl_xor_sync(0xffffffffu, acc[v], 16);

    if (half == 0) {
        float inv = 1.f / (lsum + 1e-16f);
        float o[V];
#pragma unroll
        for (int v = 0; v < V; v++)
            o[v] = fmaxf(fmaf(acc[v], inv, bias[l16 * V + v]), 0.f);
        if (V == 8) {
            float4 o0 = {o[0], o[1], o[2], o[3]};
            float4 o1 = {o[4], o[5], o[6], o[7]};
            reinterpret_cast<float4*>(out)[w * 32 + l16 * 2] = o0;
            reinterpret_cast<float4*>(out)[w * 32 + l16 * 2 + 1] = o1;
        } else {
            float4 o0 = {o[0], o[1], o[2], o[3]};
            reinterpret_cast<float4*>(out)[w * 16 + l16] = o0;
        }
    }
}

// ---------------- launch ----------------
extern "C" void kernel_launch(void* const* d_in, const int* in_sizes, int n_in,
                              void* d_out, int out_size)
{
    const float* x   = (const float*)d_in[0];
    const void*  ei  = d_in[1];
    const float *W0l = (const float*)d_in[2],  *W0r = (const float*)d_in[3];
    const float *a0  = (const float*)d_in[4],  *b0  = (const float*)d_in[5];
    const float *W1l = (const float*)d_in[6],  *W1r = (const float*)d_in[7];
    const float *a1  = (const float*)d_in[8],  *b1  = (const float*)d_in[9];
    const float *W2l = (const float*)d_in[10], *W2r = (const float*)d_in[11];
    const float *a2  = (const float*)d_in[12], *b2  = (const float*)d_in[13];
    float* out = (float*)d_out;

    void *p_hlh, *p_hr, *p_h, *p_wth;
    cudaGetSymbolAddress(&p_hlh, g_hlh);
    cudaGetSymbolAddress(&p_hr, g_hr);
    cudaGetSymbolAddress(&p_h, g_h);
    cudaGetSymbolAddress(&p_wth, g_wth);
    __half* hl  = (__half*)p_hlh;
    float*  hr  = (float*)p_hr;
    float*  h   = (float*)p_h;
    __half* wth = (__half*)p_wth;

    const dim3 gg((NN + BM - 1) / BM, 2);
    const dim3 gg2((NN + BM - 1) / BM, 1);
    const int egrid = (NN * 32 + 255) / 256;

    zero_detect_k<<<(NN + 1023) / 1024, 1024>>>((const int*)ei,
        W0l, W0r, W1l, W1r, W2l, W2r);                               // 1
    gemm0_conv_k<<<GTILES + CONVB, 256>>>(x, wth, wth + 16384,
                                          hl, hr, ei);               // 2
    scan1_k<<<NB, 1024>>>();                                         // 3
    scan3_k<<<(NN + 255) / 256, 256>>>();                            // 4
    scatter_k<<<(ET + 255) / 256, 256>>>();                          // 5
    gat_edge<4, 128><<<egrid, 256>>>(hl, hr, a0, b0, h);             // 6
    gemm_dual_k<<<gg, 256>>>(h, wth + 2 * 16384,
                             wth + 3 * 16384, hl, hr, NN, 128);      // 7
    gat_edge<4, 128><<<egrid, 256>>>(hl, hr, a1, b1, h);             // 8
    gemm_dual_k<<<gg2, 256>>>(h, wth + 4 * 16384,
                              wth + 5 * 16384, hl, hr, NN, 64);      // 9
    gat_edge<1, 64><<<egrid, 256>>>(hl, hr, a2, b2, out);            // 10
}